// round 5
// baseline (speedup 1.0000x reference)
#include <cuda_runtime.h>
#include <cuda_bf16.h>
#include <cstdint>

// ============================================================================
// VQMetaBaseline via mma.sync bf16 (compute_103-safe):
// Fused Dekker-split GEMM (hi*hi + hi*lo + lo*hi per k-tile, one fp32
// accumulator set, exact products, fixed order -> deterministic) in an
// occupancy-2 shell: 256 thr, 32KB stages x3 = 96KB -> 2 CTAs/SM.
// ============================================================================

#define IN_DIM 49152
#define NDIM   512
#define NK     512
#define MROWS  400
#define MPAD   512
#define NSHOT  100

// GEMM tiling
#define BM 128
#define BN 128
#define BK 32
#define STAGES 3
#define STG_BYTES 32768            // Ahi 8K | Alo 8K | Bhi 8K | Blo 8K
#define SMEM_GEMM (STAGES * STG_BYTES)   // 96 KB

// split-K: 18 sub-splits over 1536 k-tiles (first 6 get 86, rest 85)
#define SPLITS   18
#define KT_TOTAL (IN_DIM / BK)             // 1536
#define KT_BASE  (KT_TOTAL / SPLITS)       // 85
#define KT_REM   (KT_TOTAL % SPLITS)       // 6

// ---- scratch (static device globals; no runtime allocation) ----------------
__device__ __align__(128) __nv_bfloat16 gAhi[(size_t)MPAD * IN_DIM];
__device__ __align__(128) __nv_bfloat16 gAlo[(size_t)MPAD * IN_DIM];
__device__ __align__(128) __nv_bfloat16 gBhi[(size_t)NDIM * IN_DIM];
__device__ __align__(128) __nv_bfloat16 gBlo[(size_t)NDIM * IN_DIM];
__device__ float g_part[(size_t)SPLITS * MPAD * NDIM];
__device__ float g_ze[MROWS * NDIM];
__device__ int   g_idx[MROWS];
__device__ float g_proto[20 * NDIM];

// ---- helpers ----------------------------------------------------------------
__device__ __forceinline__ uint32_t smem_u32(const void* p) {
    uint32_t a;
    asm("{ .reg .u64 t; cvta.to.shared.u64 t, %1; cvt.u32.u64 %0, t; }"
        : "=r"(a) : "l"(p));
    return a;
}
__device__ __forceinline__ void cp16(uint32_t dst, const void* src) {
    asm volatile("cp.async.cg.shared.global [%0], [%1], 16;"
                 :: "r"(dst), "l"(src) : "memory");
}
#define CP_COMMIT() asm volatile("cp.async.commit_group;" ::: "memory")
#define CP_WAIT1()  asm volatile("cp.async.wait_group 1;" ::: "memory")

__device__ __forceinline__ void ldsm4(uint32_t* r, uint32_t a) {
    asm volatile("ldmatrix.sync.aligned.m8n8.x4.shared.b16 {%0,%1,%2,%3}, [%4];"
                 : "=r"(r[0]), "=r"(r[1]), "=r"(r[2]), "=r"(r[3]) : "r"(a));
}
__device__ __forceinline__ void mma16816(float* c, const uint32_t* a,
                                         uint32_t b0, uint32_t b1) {
    asm volatile(
        "mma.sync.aligned.m16n8k16.row.col.f32.bf16.bf16.f32 "
        "{%0,%1,%2,%3},{%4,%5,%6,%7},{%8,%9},{%0,%1,%2,%3};"
        : "+f"(c[0]), "+f"(c[1]), "+f"(c[2]), "+f"(c[3])
        : "r"(a[0]), "r"(a[1]), "r"(a[2]), "r"(a[3]), "r"(b0), "r"(b1));
}

// smem tile offset: rows x 64B (32 bf16), XOR swizzle -> conflict-free ldmatrix
__device__ __forceinline__ uint32_t toff(int r, int c) {
    return (uint32_t)(r * 64 + ((c ^ ((r >> 1) & 3)) << 4));
}

__device__ __forceinline__ void fsplit(float x, __nv_bfloat16& h, __nv_bfloat16& l) {
    h = __float2bfloat16_rn(x);
    l = __float2bfloat16_rn(x - __bfloat162float(h));
}
__device__ __forceinline__ uint32_t pack2bf(__nv_bfloat16 a, __nv_bfloat16 b) {
    __nv_bfloat162 v(a, b);
    return *reinterpret_cast<uint32_t*>(&v);
}

// ============================================================================
// conv_a: [xs;xq] fp32 -> gAhi/gAlo bf16, rows 400..511 zero-padded
// ============================================================================
__global__ __launch_bounds__(256) void conv_a(const float* __restrict__ xs,
                                              const float* __restrict__ xq) {
    size_t e = ((size_t)blockIdx.x * 256 + threadIdx.x) * 4;
    if (e >= (size_t)MPAD * IN_DIM) return;
    int row = (int)(e / IN_DIM);
    int col = (int)(e % IN_DIM);
    float4 v = make_float4(0.f, 0.f, 0.f, 0.f);
    if (row < NSHOT)      v = *(const float4*)(xs + (size_t)row * IN_DIM + col);
    else if (row < MROWS) v = *(const float4*)(xq + (size_t)(row - NSHOT) * IN_DIM + col);
    __nv_bfloat16 h0,h1,h2,h3,l0,l1,l2,l3;
    fsplit(v.x,h0,l0); fsplit(v.y,h1,l1); fsplit(v.z,h2,l2); fsplit(v.w,h3,l3);
    *(uint2*)&gAhi[e] = make_uint2(pack2bf(h0,h1), pack2bf(h2,h3));
    *(uint2*)&gAlo[e] = make_uint2(pack2bf(l0,l1), pack2bf(l2,l3));
}

// ============================================================================
// conv_b: enc_w [K,N] fp32 -> gBhi/gBlo [N,K] bf16 (transpose via smem tile)
// ============================================================================
__global__ __launch_bounds__(256) void conv_b(const float* __restrict__ W) {
    __shared__ float ts[32][33];
    const int k0 = blockIdx.x << 5;
    const int n0 = blockIdx.y << 5;
    const int t  = threadIdx.x;
    {
        int r = t >> 3, c = (t & 7) << 2;
        float4 v = *(const float4*)(W + (size_t)(k0 + r) * NDIM + n0 + c);
        ts[r][c] = v.x; ts[r][c+1] = v.y; ts[r][c+2] = v.z; ts[r][c+3] = v.w;
    }
    __syncthreads();
    int n = t >> 3, kq = (t & 7) << 2;
    __nv_bfloat16 h[4], l[4];
#pragma unroll
    for (int i = 0; i < 4; i++) fsplit(ts[kq + i][n], h[i], l[i]);
    size_t o = (size_t)(n0 + n) * IN_DIM + k0 + kq;
    *(uint2*)&gBhi[o] = make_uint2(pack2bf(h[0],h[1]), pack2bf(h[2],h[3]));
    *(uint2*)&gBlo[o] = make_uint2(pack2bf(l[0],l[1]), pack2bf(l[2],l[3]));
}

// ============================================================================
// Fused HMMA GEMM: all 3 split-products per k-tile, one accumulator set.
// grid (4 N-tiles, 4 M-tiles, 18 splits) = 288 CTAs (one wave at occ 2).
// 256 threads, 8 warps (4M x 2N), warp tile 32x64.
// ============================================================================
__global__ __launch_bounds__(256, 2) void gemm_fused() {
    extern __shared__ char smem[];
    const uint32_t sbase = smem_u32(smem);
    const int t = threadIdx.x;
    const int wid = t >> 5, lane = t & 31;

    const int n0 = blockIdx.x * BN;
    const int m0 = blockIdx.y * BM;
    const int sp = blockIdx.z;
    const int kt0 = sp * KT_BASE + (sp < KT_REM ? sp : KT_REM);
    const int NT  = KT_BASE + (sp < KT_REM ? 1 : 0);
    const size_t k0 = (size_t)kt0 * BK;

    // ---- loader mapping: 128 rows x 4 chunks(16B); thread t -> row t>>1,
    //      chunks lc, lc+1; same pattern for all four 8KB quadrants.
    const int lr = t >> 1;
    const int lc = (t & 1) << 1;
    const uint32_t d0 = toff(lr, lc);
    const uint32_t d1 = toff(lr, lc + 1);
    const __nv_bfloat16* pAhi = gAhi + (size_t)(m0 + lr) * IN_DIM + k0 + lc * 8;
    const __nv_bfloat16* pAlo = gAlo + (size_t)(m0 + lr) * IN_DIM + k0 + lc * 8;
    const __nv_bfloat16* pBhi = gBhi + (size_t)(n0 + lr) * IN_DIM + k0 + lc * 8;
    const __nv_bfloat16* pBlo = gBlo + (size_t)(n0 + lr) * IN_DIM + k0 + lc * 8;

#define LOAD_STAGE(s, kt) do {                                          \
        const uint32_t sb_ = sbase + (s) * STG_BYTES;                    \
        const size_t ko_ = (size_t)(kt) * BK;                            \
        cp16(sb_ + d0,          pAhi + ko_);                             \
        cp16(sb_ + d1,          pAhi + ko_ + 8);                         \
        cp16(sb_ + 8192  + d0,  pAlo + ko_);                             \
        cp16(sb_ + 8192  + d1,  pAlo + ko_ + 8);                         \
        cp16(sb_ + 16384 + d0,  pBhi + ko_);                             \
        cp16(sb_ + 16384 + d1,  pBhi + ko_ + 8);                         \
        cp16(sb_ + 24576 + d0,  pBlo + ko_);                             \
        cp16(sb_ + 24576 + d1,  pBlo + ko_ + 8);                         \
    } while (0)

    // ---- compute mapping: warp (wm, wn) owns 32x64 of C
    const int wm = wid >> 1, wn = wid & 1;
    const int fr = lane & 15, fc = lane >> 4;
    uint32_t aoff[2][2], boff[4][2];
#pragma unroll
    for (int mh = 0; mh < 2; mh++)
#pragma unroll
        for (int ks = 0; ks < 2; ks++)
            aoff[mh][ks] = toff(wm * 32 + mh * 16 + fr, ks * 2 + fc);
#pragma unroll
    for (int p = 0; p < 4; p++)
#pragma unroll
        for (int ks = 0; ks < 2; ks++)
            boff[p][ks] = toff(wn * 64 + p * 16 + fr, ks * 2 + fc);

    float c[2][8][4];
#pragma unroll
    for (int i = 0; i < 2; i++)
#pragma unroll
        for (int j = 0; j < 8; j++)
#pragma unroll
            for (int k = 0; k < 4; k++) c[i][j][k] = 0.f;

    // ---- prologue: stages 0,1
    LOAD_STAGE(0, 0); CP_COMMIT();
    LOAD_STAGE(1, 1); CP_COMMIT();

    // ---- main loop (3-stage ring, 2 in flight)
    int s_cur = 0, s_load = 2;
    for (int kt = 0; kt < NT; ++kt) {
        CP_WAIT1();
        __syncthreads();

        if (kt + 2 < NT)
            LOAD_STAGE(s_load, kt + 2);
        CP_COMMIT();

        const uint32_t sb = sbase + s_cur * STG_BYTES;
#pragma unroll
        for (int ks = 0; ks < 2; ks++) {
            uint32_t ah[2][4], al[2][4];
            ldsm4(ah[0], sb + aoff[0][ks]);
            ldsm4(ah[1], sb + aoff[1][ks]);
            ldsm4(al[0], sb + 8192 + aoff[0][ks]);
            ldsm4(al[1], sb + 8192 + aoff[1][ks]);
#pragma unroll
            for (int p = 0; p < 4; p++) {
                uint32_t bh[4], bl[4];
                ldsm4(bh, sb + 16384 + boff[p][ks]);
                ldsm4(bl, sb + 24576 + boff[p][ks]);
#pragma unroll
                for (int mh = 0; mh < 2; mh++) {
                    mma16816(c[mh][2*p],     ah[mh], bh[0], bh[2]);  // hi*hi
                    mma16816(c[mh][2*p + 1], ah[mh], bh[1], bh[3]);
                    mma16816(c[mh][2*p],     ah[mh], bl[0], bl[2]);  // hi*lo
                    mma16816(c[mh][2*p + 1], ah[mh], bl[1], bl[3]);
                    mma16816(c[mh][2*p],     al[mh], bh[0], bh[2]);  // lo*hi
                    mma16816(c[mh][2*p + 1], al[mh], bh[1], bh[3]);
                }
            }
        }
        s_cur = (s_cur == 2) ? 0 : s_cur + 1;
        s_load = (s_load == 2) ? 0 : s_load + 1;
    }

    // ---- epilogue: direct fp32 stores of partials
    float* base = g_part + (size_t)sp * MPAD * NDIM;
    const int row0 = m0 + wm * 32 + (lane >> 2);
    const int col0 = n0 + wn * 64 + (lane & 3) * 2;
#pragma unroll
    for (int mi = 0; mi < 2; mi++)
#pragma unroll
        for (int j = 0; j < 8; j++) {
            const int r = row0 + mi * 16;
            const int cc = col0 + j * 8;
            *(float2*)&base[(size_t)r * NDIM + cc]       = make_float2(c[mi][j][0], c[mi][j][1]);
            *(float2*)&base[(size_t)(r + 8) * NDIM + cc] = make_float2(c[mi][j][2], c[mi][j][3]);
        }
}

// ============================================================================
// split-K reduce + bias (deterministic order, float4-vectorized)
// ============================================================================
__global__ void reduce_bias(const float* __restrict__ bias) {
    const int i4 = blockIdx.x * blockDim.x + threadIdx.x;
    const int e = i4 * 4;
    if (e >= MROWS * NDIM) return;
    const int n = e & (NDIM - 1);
    float4 s = make_float4(0.f, 0.f, 0.f, 0.f);
#pragma unroll
    for (int p = 0; p < SPLITS; p++) {
        const float4 v = *(const float4*)&g_part[(size_t)p * MPAD * NDIM + e];
        s.x += v.x; s.y += v.y; s.z += v.z; s.w += v.w;
    }
    const float4 b = *(const float4*)&bias[n];
    s.x += b.x; s.y += b.y; s.z += b.z; s.w += b.w;
    *(float4*)&g_ze[e] = s;
}

// ============================================================================
// nearest codebook: argmax_k (z.c_k - 0.5||c_k||^2), tie -> min k
// ============================================================================
__global__ __launch_bounds__(512) void nearest_kernel(const float* __restrict__ cb) {
    __shared__ float zs[8][NDIM];
    __shared__ float red[512];
    __shared__ int   redi[512];
    const int t = threadIdx.x;
    const int r0 = blockIdx.x * 8;
#pragma unroll
    for (int g = 0; g < 8; g++) zs[g][t] = g_ze[(r0 + g) * NDIM + t];
    __syncthreads();
    float s[8];
#pragma unroll
    for (int g = 0; g < 8; g++) s[g] = 0.f;
    float cn = 0.f;
#pragma unroll 4
    for (int d = 0; d < NDIM; d++) {
        const float c = cb[d * NK + t];
        cn = fmaf(c, c, cn);
#pragma unroll
        for (int g = 0; g < 8; g++) s[g] = fmaf(zs[g][d], c, s[g]);
    }
    for (int g = 0; g < 8; g++) {
        red[t] = s[g] - 0.5f * cn;
        redi[t] = t;
        __syncthreads();
        for (int off = 256; off > 0; off >>= 1) {
            if (t < off) {
                const float o = red[t + off];
                const int oi = redi[t + off];
                if (o > red[t] || (o == red[t] && oi < redi[t])) { red[t] = o; redi[t] = oi; }
            }
            __syncthreads();
        }
        if (t == 0) g_idx[r0 + g] = redi[0];
        __syncthreads();
    }
}

// ============================================================================
// prototypes: mean of 5 quantized shots, L2-normalized
// ============================================================================
__global__ __launch_bounds__(512) void proto_kernel(const float* __restrict__ cb) {
    const int bw = blockIdx.x, t = threadIdx.x;
    float p = 0.f;
#pragma unroll
    for (int s = 0; s < 5; s++) p += cb[(size_t)t * NK + g_idx[bw * 5 + s]];
    p *= 0.2f;
    __shared__ float red[512];
    red[t] = p * p;
    __syncthreads();
    for (int off = 256; off > 0; off >>= 1) {
        if (t < off) red[t] += red[t + off];
        __syncthreads();
    }
    g_proto[bw * NDIM + t] = p * rsqrtf(red[0]);
}

// ============================================================================
// logits
// ============================================================================
__global__ __launch_bounds__(512) void logits_kernel(
    const float* __restrict__ cb, const float* __restrict__ tptr,
    float* __restrict__ out) {
    const int bq = blockIdx.x, t = threadIdx.x;
    const int b = bq / 75;
    const float v = cb[(size_t)t * NK + g_idx[NSHOT + bq]];
    __shared__ float red[512];
    red[t] = v * v;
    __syncthreads();
    for (int off = 256; off > 0; off >>= 1) {
        if (t < off) red[t] += red[t + off];
        __syncthreads();
    }
    const float vn = v * rsqrtf(red[0]);
    const float temp = *tptr;
    for (int w = 0; w < 5; w++) {
        __syncthreads();
        red[t] = vn * g_proto[(b * 5 + w) * NDIM + t];
        __syncthreads();
        for (int off = 256; off > 0; off >>= 1) {
            if (t < off) red[t] += red[t + off];
            __syncthreads();
        }
        if (t == 0) out[bq * 5 + w] = red[0] * temp;
    }
}

// ============================================================================
extern "C" void kernel_launch(void* const* d_in, const int* in_sizes, int n_in,
                              void* d_out, int out_size) {
    const float* xs   = (const float*)d_in[0];
    const float* xq   = (const float*)d_in[1];
    const float* W    = (const float*)d_in[2];
    const float* bias = (const float*)d_in[3];
    const float* cb   = (const float*)d_in[4];
    const float* temp = (const float*)d_in[5];
    float* out = (float*)d_out;

    cudaFuncSetAttribute(gemm_fused, cudaFuncAttributeMaxDynamicSharedMemorySize,
                         SMEM_GEMM);

    conv_a<<<(int)(((size_t)MPAD * IN_DIM / 4 + 255) / 256), 256>>>(xs, xq);
    conv_b<<<dim3(IN_DIM / 32, NDIM / 32), 256>>>(W);
    gemm_fused<<<dim3(NDIM / BN, MPAD / BM, SPLITS), 256, SMEM_GEMM>>>();
    reduce_bias<<<(MROWS * NDIM / 4 + 255) / 256, 256>>>(bias);
    nearest_kernel<<<MROWS / 8, 512>>>(cb);
    proto_kernel<<<20, 512>>>(cb);
    logits_kernel<<<300, 512>>>(cb, temp, out);
}

// round 6
// speedup vs baseline: 1.0748x; 1.0748x over previous
#include <cuda_runtime.h>
#include <cuda_bf16.h>
#include <cstdint>

// ============================================================================
// VQMetaBaseline via mma.sync bf16 (compute_103-safe; R3 structure):
// z_e = X @ W + b with bf16 hi/lo Dekker split, 3 exact-product passes
// (hi*hi + hi*lo + lo*hi) as separate grid-z phases, fp32 accumulate ->
// argmin-index parity with fp32 reference. 5-stage cp.async pipeline.
// ============================================================================

#define IN_DIM 49152
#define NDIM   512
#define NK     512
#define MROWS  400
#define MPAD   512
#define NSHOT  100

// GEMM tiling
#define BM 128
#define BN 128
#define BK 32
#define STAGES 5
#define STG_BYTES 16384            // A 8KB + B 8KB per stage
#define SMEM_GEMM (STAGES * STG_BYTES)   // 80 KB -> 2 CTAs/SM

// split-K: 3 phases (hihi, hilo, lohi) x 6 sub-splits
#define SUBSPLITS 6
#define TOTSPLITS 18
#define KSPLIT (IN_DIM / SUBSPLITS)      // 8192
#define NT (KSPLIT / BK)                 // 256 k-tiles per CTA

// ---- scratch (static device globals; no runtime allocation) ----------------
__device__ __align__(128) __nv_bfloat16 gAhi[(size_t)MPAD * IN_DIM];
__device__ __align__(128) __nv_bfloat16 gAlo[(size_t)MPAD * IN_DIM];
__device__ __align__(128) __nv_bfloat16 gBhi[(size_t)NDIM * IN_DIM];
__device__ __align__(128) __nv_bfloat16 gBlo[(size_t)NDIM * IN_DIM];
__device__ float g_part[(size_t)TOTSPLITS * MPAD * NDIM];
__device__ float g_ze[MROWS * NDIM];
__device__ int   g_idx[MROWS];
__device__ float g_proto[20 * NDIM];

// ---- helpers ----------------------------------------------------------------
__device__ __forceinline__ uint32_t smem_u32(const void* p) {
    uint32_t a;
    asm("{ .reg .u64 t; cvta.to.shared.u64 t, %1; cvt.u32.u64 %0, t; }"
        : "=r"(a) : "l"(p));
    return a;
}
__device__ __forceinline__ void cp16(uint32_t dst, const void* src) {
    asm volatile("cp.async.cg.shared.global [%0], [%1], 16;"
                 :: "r"(dst), "l"(src) : "memory");
}
#define CP_COMMIT() asm volatile("cp.async.commit_group;" ::: "memory")
#define CP_WAIT3()  asm volatile("cp.async.wait_group 3;" ::: "memory")

__device__ __forceinline__ void ldsm4(uint32_t& r0, uint32_t& r1,
                                      uint32_t& r2, uint32_t& r3, uint32_t a) {
    asm volatile("ldmatrix.sync.aligned.m8n8.x4.shared.b16 {%0,%1,%2,%3}, [%4];"
                 : "=r"(r0), "=r"(r1), "=r"(r2), "=r"(r3) : "r"(a));
}
__device__ __forceinline__ void mma16816(float* c, const uint32_t* a,
                                         const uint32_t* b) {
    asm volatile(
        "mma.sync.aligned.m16n8k16.row.col.f32.bf16.bf16.f32 "
        "{%0,%1,%2,%3},{%4,%5,%6,%7},{%8,%9},{%0,%1,%2,%3};"
        : "+f"(c[0]), "+f"(c[1]), "+f"(c[2]), "+f"(c[3])
        : "r"(a[0]), "r"(a[1]), "r"(a[2]), "r"(a[3]), "r"(b[0]), "r"(b[1]));
}

// smem tile offset: 128 rows x 64B (32 bf16), XOR swizzle -> conflict-free
__device__ __forceinline__ uint32_t toff(int r, int c) {
    return (uint32_t)(r * 64 + ((c ^ ((r >> 1) & 3)) << 4));
}

__device__ __forceinline__ void fsplit(float x, __nv_bfloat16& h, __nv_bfloat16& l) {
    h = __float2bfloat16_rn(x);
    l = __float2bfloat16_rn(x - __bfloat162float(h));
}
__device__ __forceinline__ uint32_t pack2bf(__nv_bfloat16 a, __nv_bfloat16 b) {
    __nv_bfloat162 v(a, b);
    return *reinterpret_cast<uint32_t*>(&v);
}

// ============================================================================
// conv_a: [xs;xq] fp32 -> gAhi/gAlo bf16, rows 400..511 zero-padded
// ============================================================================
__global__ __launch_bounds__(256) void conv_a(const float* __restrict__ xs,
                                              const float* __restrict__ xq) {
    size_t e = ((size_t)blockIdx.x * 256 + threadIdx.x) * 4;
    if (e >= (size_t)MPAD * IN_DIM) return;
    int row = (int)(e / IN_DIM);
    int col = (int)(e % IN_DIM);
    float4 v = make_float4(0.f, 0.f, 0.f, 0.f);
    if (row < NSHOT)      v = *(const float4*)(xs + (size_t)row * IN_DIM + col);
    else if (row < MROWS) v = *(const float4*)(xq + (size_t)(row - NSHOT) * IN_DIM + col);
    __nv_bfloat16 h0,h1,h2,h3,l0,l1,l2,l3;
    fsplit(v.x,h0,l0); fsplit(v.y,h1,l1); fsplit(v.z,h2,l2); fsplit(v.w,h3,l3);
    *(uint2*)&gAhi[e] = make_uint2(pack2bf(h0,h1), pack2bf(h2,h3));
    *(uint2*)&gAlo[e] = make_uint2(pack2bf(l0,l1), pack2bf(l2,l3));
}

// ============================================================================
// conv_b: enc_w [K,N] fp32 -> gBhi/gBlo [N,K] bf16 (transpose via smem tile)
// ============================================================================
__global__ __launch_bounds__(256) void conv_b(const float* __restrict__ W) {
    __shared__ float ts[32][33];
    const int k0 = blockIdx.x << 5;
    const int n0 = blockIdx.y << 5;
    const int t  = threadIdx.x;
    {
        int r = t >> 3, c = (t & 7) << 2;
        float4 v = *(const float4*)(W + (size_t)(k0 + r) * NDIM + n0 + c);
        ts[r][c] = v.x; ts[r][c+1] = v.y; ts[r][c+2] = v.z; ts[r][c+3] = v.w;
    }
    __syncthreads();
    int n = t >> 3, kq = (t & 7) << 2;
    __nv_bfloat16 h[4], l[4];
#pragma unroll
    for (int i = 0; i < 4; i++) fsplit(ts[kq + i][n], h[i], l[i]);
    size_t o = (size_t)(n0 + n) * IN_DIM + k0 + kq;
    *(uint2*)&gBhi[o] = make_uint2(pack2bf(h[0],h[1]), pack2bf(h[2],h[3]));
    *(uint2*)&gBlo[o] = make_uint2(pack2bf(l[0],l[1]), pack2bf(l[2],l[3]));
}

// ============================================================================
// noop: launch-order shim so gemm_hmma is launch #4 (the one ncu captures)
// ============================================================================
__global__ void noop_kernel() {}

// ============================================================================
// HMMA GEMM (R3 structure): g_part[sp] = A_ph @ B_ph^T over k slice
// grid (4 N-tiles, 4 M-tiles, 18 splits), 256 threads, 8 warps (4M x 2N).
// 5-stage cp.async pipeline, 4 loads in flight.
// ============================================================================
__global__ __launch_bounds__(256, 2) void gemm_hmma() {
    extern __shared__ char smem[];
    const uint32_t sbase = smem_u32(smem);
    const int t = threadIdx.x;
    const int wid = t >> 5, lane = t & 31;

    const int n0 = blockIdx.x * BN;
    const int m0 = blockIdx.y * BM;
    const int sp = blockIdx.z;
    const int phase = sp / SUBSPLITS;            // 0: hi*hi  1: hi*lo  2: lo*hi
    const size_t ksub = (size_t)(sp % SUBSPLITS) * KSPLIT;

    const __nv_bfloat16* __restrict__ A = (phase == 2) ? gAlo : gAhi;
    const __nv_bfloat16* __restrict__ B = (phase == 1) ? gBlo : gBhi;

    // ---- loader mapping: thread loads 2 A chunks + 2 B chunks of 16B per stage
    const int lr = t >> 2;          // tile row 0..63
    const int lc = t & 3;           // 16B chunk 0..3
    const uint32_t dA1 = toff(lr, lc),        dA2 = toff(lr + 64, lc);
    const uint32_t dB1 = toff(lr, lc) + 8192, dB2 = toff(lr + 64, lc) + 8192;
    const __nv_bfloat16* pA1 = A + (size_t)(m0 + lr) * IN_DIM + ksub + lc * 8;
    const __nv_bfloat16* pA2 = pA1 + (size_t)64 * IN_DIM;
    const __nv_bfloat16* pB1 = B + (size_t)(n0 + lr) * IN_DIM + ksub + lc * 8;
    const __nv_bfloat16* pB2 = pB1 + (size_t)64 * IN_DIM;

#define LOAD_STAGE(s, kt) do {                                        \
        const uint32_t sb_ = sbase + (s) * STG_BYTES;                  \
        const size_t ko_ = (size_t)(kt) * BK;                          \
        cp16(sb_ + dA1, pA1 + ko_); cp16(sb_ + dA2, pA2 + ko_);        \
        cp16(sb_ + dB1, pB1 + ko_); cp16(sb_ + dB2, pB2 + ko_);        \
    } while (0)

    // ---- compute mapping: warp (wm, wn) owns 32x64 of C
    const int wm = wid >> 1, wn = wid & 1;
    const int fr = lane & 15, fc = lane >> 4;
    uint32_t aoff[2][2], boff[4][2];
#pragma unroll
    for (int mh = 0; mh < 2; mh++)
#pragma unroll
        for (int ks = 0; ks < 2; ks++)
            aoff[mh][ks] = toff(wm * 32 + mh * 16 + fr, ks * 2 + fc);
#pragma unroll
    for (int p = 0; p < 4; p++)
#pragma unroll
        for (int ks = 0; ks < 2; ks++)
            boff[p][ks] = 8192 + toff(wn * 64 + p * 16 + fr, ks * 2 + fc);

    float c[2][8][4];
#pragma unroll
    for (int i = 0; i < 2; i++)
#pragma unroll
        for (int j = 0; j < 8; j++)
#pragma unroll
            for (int k = 0; k < 4; k++) c[i][j][k] = 0.f;

    // ---- prologue: fill stages 0..3
#pragma unroll
    for (int s = 0; s < STAGES - 1; s++) {
        LOAD_STAGE(s, s);
        CP_COMMIT();
    }

    // ---- main loop (5-stage ring, 4 in flight)
    int s_cur = 0, s_load = STAGES - 1;
    for (int kt = 0; kt < NT; ++kt) {
        CP_WAIT3();
        __syncthreads();

        if (kt + STAGES - 1 < NT)
            LOAD_STAGE(s_load, kt + STAGES - 1);
        CP_COMMIT();

        const uint32_t sb = sbase + s_cur * STG_BYTES;
#pragma unroll
        for (int ks = 0; ks < 2; ks++) {
            uint32_t a0[4], a1[4];
            ldsm4(a0[0], a0[1], a0[2], a0[3], sb + aoff[0][ks]);
            ldsm4(a1[0], a1[1], a1[2], a1[3], sb + aoff[1][ks]);
#pragma unroll
            for (int p = 0; p < 4; p++) {
                uint32_t r0, r1, r2, r3;
                ldsm4(r0, r1, r2, r3, sb + boff[p][ks]);
                uint32_t b0[2] = { r0, r2 };
                uint32_t b1[2] = { r1, r3 };
                mma16816(c[0][2*p],     a0, b0);
                mma16816(c[1][2*p],     a1, b0);
                mma16816(c[0][2*p + 1], a0, b1);
                mma16816(c[1][2*p + 1], a1, b1);
            }
        }
        s_cur  = (s_cur  == STAGES - 1) ? 0 : s_cur + 1;
        s_load = (s_load == STAGES - 1) ? 0 : s_load + 1;
    }

    // ---- epilogue: direct fp32 stores of partials
    float* base = g_part + (size_t)sp * MPAD * NDIM;
    const int row0 = m0 + wm * 32 + (lane >> 2);
    const int col0 = n0 + wn * 64 + (lane & 3) * 2;
#pragma unroll
    for (int mi = 0; mi < 2; mi++)
#pragma unroll
        for (int j = 0; j < 8; j++) {
            const int r = row0 + mi * 16;
            const int cc = col0 + j * 8;
            *(float2*)&base[(size_t)r * NDIM + cc]       = make_float2(c[mi][j][0], c[mi][j][1]);
            *(float2*)&base[(size_t)(r + 8) * NDIM + cc] = make_float2(c[mi][j][2], c[mi][j][3]);
        }
}

// ============================================================================
// split-K reduce + bias (deterministic order, float4-vectorized)
// ============================================================================
__global__ void reduce_bias(const float* __restrict__ bias) {
    const int i4 = blockIdx.x * blockDim.x + threadIdx.x;
    const int e = i4 * 4;
    if (e >= MROWS * NDIM) return;
    const int n = e & (NDIM - 1);
    float4 s = make_float4(0.f, 0.f, 0.f, 0.f);
#pragma unroll
    for (int p = 0; p < TOTSPLITS; p++) {
        const float4 v = *(const float4*)&g_part[(size_t)p * MPAD * NDIM + e];
        s.x += v.x; s.y += v.y; s.z += v.z; s.w += v.w;
    }
    const float4 b = *(const float4*)&bias[n];
    s.x += b.x; s.y += b.y; s.z += b.z; s.w += b.w;
    *(float4*)&g_ze[e] = s;
}

// ============================================================================
// nearest codebook: argmax_k (z.c_k - 0.5||c_k||^2), tie -> min k
// ============================================================================
__global__ __launch_bounds__(512) void nearest_kernel(const float* __restrict__ cb) {
    __shared__ float zs[8][NDIM];
    __shared__ float red[512];
    __shared__ int   redi[512];
    const int t = threadIdx.x;
    const int r0 = blockIdx.x * 8;
#pragma unroll
    for (int g = 0; g < 8; g++) zs[g][t] = g_ze[(r0 + g) * NDIM + t];
    __syncthreads();
    float s[8];
#pragma unroll
    for (int g = 0; g < 8; g++) s[g] = 0.f;
    float cn = 0.f;
#pragma unroll 4
    for (int d = 0; d < NDIM; d++) {
        const float c = cb[d * NK + t];
        cn = fmaf(c, c, cn);
#pragma unroll
        for (int g = 0; g < 8; g++) s[g] = fmaf(zs[g][d], c, s[g]);
    }
    for (int g = 0; g < 8; g++) {
        red[t] = s[g] - 0.5f * cn;
        redi[t] = t;
        __syncthreads();
        for (int off = 256; off > 0; off >>= 1) {
            if (t < off) {
                const float o = red[t + off];
                const int oi = redi[t + off];
                if (o > red[t] || (o == red[t] && oi < redi[t])) { red[t] = o; redi[t] = oi; }
            }
            __syncthreads();
        }
        if (t == 0) g_idx[r0 + g] = redi[0];
        __syncthreads();
    }
}

// ============================================================================
// prototypes: mean of 5 quantized shots, L2-normalized
// ============================================================================
__global__ __launch_bounds__(512) void proto_kernel(const float* __restrict__ cb) {
    const int bw = blockIdx.x, t = threadIdx.x;
    float p = 0.f;
#pragma unroll
    for (int s = 0; s < 5; s++) p += cb[(size_t)t * NK + g_idx[bw * 5 + s]];
    p *= 0.2f;
    __shared__ float red[512];
    red[t] = p * p;
    __syncthreads();
    for (int off = 256; off > 0; off >>= 1) {
        if (t < off) red[t] += red[t + off];
        __syncthreads();
    }
    g_proto[bw * NDIM + t] = p * rsqrtf(red[0]);
}

// ============================================================================
// logits
// ============================================================================
__global__ __launch_bounds__(512) void logits_kernel(
    const float* __restrict__ cb, const float* __restrict__ tptr,
    float* __restrict__ out) {
    const int bq = blockIdx.x, t = threadIdx.x;
    const int b = bq / 75;
    const float v = cb[(size_t)t * NK + g_idx[NSHOT + bq]];
    __shared__ float red[512];
    red[t] = v * v;
    __syncthreads();
    for (int off = 256; off > 0; off >>= 1) {
        if (t < off) red[t] += red[t + off];
        __syncthreads();
    }
    const float vn = v * rsqrtf(red[0]);
    const float temp = *tptr;
    for (int w = 0; w < 5; w++) {
        __syncthreads();
        red[t] = vn * g_proto[(b * 5 + w) * NDIM + t];
        __syncthreads();
        for (int off = 256; off > 0; off >>= 1) {
            if (t < off) red[t] += red[t + off];
            __syncthreads();
        }
        if (t == 0) out[bq * 5 + w] = red[0] * temp;
    }
}

// ============================================================================
extern "C" void kernel_launch(void* const* d_in, const int* in_sizes, int n_in,
                              void* d_out, int out_size) {
    const float* xs   = (const float*)d_in[0];
    const float* xq   = (const float*)d_in[1];
    const float* W    = (const float*)d_in[2];
    const float* bias = (const float*)d_in[3];
    const float* cb   = (const float*)d_in[4];
    const float* temp = (const float*)d_in[5];
    float* out = (float*)d_out;

    cudaFuncSetAttribute(gemm_hmma, cudaFuncAttributeMaxDynamicSharedMemorySize,
                         SMEM_GEMM);

    conv_a<<<(int)(((size_t)MPAD * IN_DIM / 4 + 255) / 256), 256>>>(xs, xq);
    conv_b<<<dim3(IN_DIM / 32, NDIM / 32), 256>>>(W);
    noop_kernel<<<1, 32>>>();   // shim: makes gemm_hmma launch #4 (ncu target)
    gemm_hmma<<<dim3(NDIM / BN, MPAD / BM, TOTSPLITS), 256, SMEM_GEMM>>>();
    reduce_bias<<<(MROWS * NDIM / 4 + 255) / 256, 256>>>(bias);
    nearest_kernel<<<MROWS / 8, 512>>>(cb);
    proto_kernel<<<20, 512>>>(cb);
    logits_kernel<<<300, 512>>>(cb, temp, out);
}

// round 7
// speedup vs baseline: 1.1457x; 1.0660x over previous
#include <cuda_runtime.h>
#include <cuda_bf16.h>
#include <cstdint>

// ============================================================================
// VQMetaBaseline via mma.sync bf16 (compute_103-safe; R3 GEMM structure):
// z_e = X @ W + b with bf16 hi/lo Dekker split, 3 exact-product passes
// (hi*hi + hi*lo + lo*hi) as separate grid-z phases, fp32 accumulate ->
// argmin-index parity with fp32 reference. Conversions merged into one
// wide-access kernel. Then nearest codebook, prototypes, cosine logits.
// ============================================================================

#define IN_DIM 49152
#define NDIM   512
#define NK     512
#define MROWS  400
#define MPAD   512
#define NSHOT  100

// GEMM tiling (R3-proven config)
#define BM 128
#define BN 128
#define BK 32
#define STAGES 4
#define STG_BYTES 16384            // A 8KB + B 8KB per stage
#define SMEM_GEMM (STAGES * STG_BYTES)   // 64 KB -> 2 CTAs/SM

// split-K: 3 phases (hihi, hilo, lohi) x 6 sub-splits
#define SUBSPLITS 6
#define TOTSPLITS 18
#define KSPLIT (IN_DIM / SUBSPLITS)      // 8192
#define NT (KSPLIT / BK)                 // 256 k-tiles per CTA

// conv_all work partition
#define A_BLOCKS ((int)((size_t)MPAD * IN_DIM / (256 * 8)))   // 12288
#define B_KT     (IN_DIM / 64)                                // 768
#define B_BLOCKS (B_KT * (NDIM / 64))                         // 6144

// ---- scratch (static device globals; no runtime allocation) ----------------
__device__ __align__(128) __nv_bfloat16 gAhi[(size_t)MPAD * IN_DIM];
__device__ __align__(128) __nv_bfloat16 gAlo[(size_t)MPAD * IN_DIM];
__device__ __align__(128) __nv_bfloat16 gBhi[(size_t)NDIM * IN_DIM];
__device__ __align__(128) __nv_bfloat16 gBlo[(size_t)NDIM * IN_DIM];
__device__ float g_part[(size_t)TOTSPLITS * MPAD * NDIM];
__device__ float g_ze[MROWS * NDIM];
__device__ int   g_idx[MROWS];
__device__ float g_proto[20 * NDIM];

// ---- helpers ----------------------------------------------------------------
__device__ __forceinline__ uint32_t smem_u32(const void* p) {
    uint32_t a;
    asm("{ .reg .u64 t; cvta.to.shared.u64 t, %1; cvt.u32.u64 %0, t; }"
        : "=r"(a) : "l"(p));
    return a;
}
__device__ __forceinline__ void cp16(uint32_t dst, const void* src) {
    asm volatile("cp.async.cg.shared.global [%0], [%1], 16;"
                 :: "r"(dst), "l"(src) : "memory");
}
#define CP_COMMIT() asm volatile("cp.async.commit_group;" ::: "memory")
#define CP_WAIT2()  asm volatile("cp.async.wait_group 2;" ::: "memory")

__device__ __forceinline__ void ldsm4(uint32_t& r0, uint32_t& r1,
                                      uint32_t& r2, uint32_t& r3, uint32_t a) {
    asm volatile("ldmatrix.sync.aligned.m8n8.x4.shared.b16 {%0,%1,%2,%3}, [%4];"
                 : "=r"(r0), "=r"(r1), "=r"(r2), "=r"(r3) : "r"(a));
}
__device__ __forceinline__ void mma16816(float* c, const uint32_t* a,
                                         const uint32_t* b) {
    asm volatile(
        "mma.sync.aligned.m16n8k16.row.col.f32.bf16.bf16.f32 "
        "{%0,%1,%2,%3},{%4,%5,%6,%7},{%8,%9},{%0,%1,%2,%3};"
        : "+f"(c[0]), "+f"(c[1]), "+f"(c[2]), "+f"(c[3])
        : "r"(a[0]), "r"(a[1]), "r"(a[2]), "r"(a[3]), "r"(b[0]), "r"(b[1]));
}

// smem tile offset: 128 rows x 64B (32 bf16), XOR swizzle -> conflict-free
__device__ __forceinline__ uint32_t toff(int r, int c) {
    return (uint32_t)(r * 64 + ((c ^ ((r >> 1) & 3)) << 4));
}

__device__ __forceinline__ void fsplit(float x, __nv_bfloat16& h, __nv_bfloat16& l) {
    h = __float2bfloat16_rn(x);
    l = __float2bfloat16_rn(x - __bfloat162float(h));
}
__device__ __forceinline__ uint32_t pack2bf(__nv_bfloat16 a, __nv_bfloat16 b) {
    __nv_bfloat162 v(a, b);
    return *reinterpret_cast<uint32_t*>(&v);
}
// split 8 consecutive floats -> uint4 hi bits + uint4 lo bits
__device__ __forceinline__ void split8(const float* f, uint4& hv, uint4& lv) {
    __nv_bfloat16 h[8], l[8];
#pragma unroll
    for (int i = 0; i < 8; i++) fsplit(f[i], h[i], l[i]);
    hv = make_uint4(pack2bf(h[0],h[1]), pack2bf(h[2],h[3]),
                    pack2bf(h[4],h[5]), pack2bf(h[6],h[7]));
    lv = make_uint4(pack2bf(l[0],l[1]), pack2bf(l[2],l[3]),
                    pack2bf(l[4],l[5]), pack2bf(l[6],l[7]));
}

// ============================================================================
// conv_all: one launch for both conversions.
//  blocks [0, A_BLOCKS):      A rows fp32 -> gAhi/gAlo (8 elems/thread)
//  blocks [A_BLOCKS, +B_BLOCKS): W [K,N] -> gBhi/gBlo [N,K] via 64x64 transpose
// ============================================================================
__global__ __launch_bounds__(256) void conv_all(const float* __restrict__ xs,
                                                const float* __restrict__ xq,
                                                const float* __restrict__ W) {
    __shared__ float ts[64][65];
    const int t = threadIdx.x;
    int bid = blockIdx.x;

    if (bid < A_BLOCKS) {
        // ---- A conversion: 2048 elems per block, 8 per thread
        const size_t e = ((size_t)bid * 256 + t) * 8;
        const int row = (int)(e / IN_DIM);
        const int col = (int)(e % IN_DIM);
        float f[8];
        if (row < NSHOT) {
            *(float4*)&f[0] = *(const float4*)(xs + (size_t)row * IN_DIM + col);
            *(float4*)&f[4] = *(const float4*)(xs + (size_t)row * IN_DIM + col + 4);
        } else if (row < MROWS) {
            const float* src = xq + (size_t)(row - NSHOT) * IN_DIM + col;
            *(float4*)&f[0] = *(const float4*)src;
            *(float4*)&f[4] = *(const float4*)(src + 4);
        } else {
#pragma unroll
            for (int i = 0; i < 8; i++) f[i] = 0.f;
        }
        uint4 hv, lv;
        split8(f, hv, lv);
        *(uint4*)&gAhi[e] = hv;
        *(uint4*)&gAlo[e] = lv;
        return;
    }

    // ---- B transpose + conversion: 64x64 fp32 tile
    bid -= A_BLOCKS;
    const int k0 = (bid % B_KT) * 64;
    const int n0 = (bid / B_KT) * 64;

    // load 64 rows x 64 cols (each thread 4 float4s)
#pragma unroll
    for (int i = 0; i < 4; i++) {
        const int r = i * 16 + (t >> 4);
        const int c = (t & 15) * 4;
        const float4 v = *(const float4*)(W + (size_t)(k0 + r) * NDIM + n0 + c);
        ts[r][c] = v.x; ts[r][c+1] = v.y; ts[r][c+2] = v.z; ts[r][c+3] = v.w;
    }
    __syncthreads();

    // store transposed: thread -> n row t>>2, k chunk (t&3)*16
    const int n  = t >> 2;
    const int kc = (t & 3) * 16;
    float f[16];
#pragma unroll
    for (int j = 0; j < 16; j++) f[j] = ts[kc + j][n];
    uint4 hv0, lv0, hv1, lv1;
    split8(f,     hv0, lv0);
    split8(f + 8, hv1, lv1);
    const size_t o = (size_t)(n0 + n) * IN_DIM + k0 + kc;
    *(uint4*)&gBhi[o]     = hv0;
    *(uint4*)&gBhi[o + 8] = hv1;
    *(uint4*)&gBlo[o]     = lv0;
    *(uint4*)&gBlo[o + 8] = lv1;
}

// ============================================================================
// noop: launch-order shims so gemm_hmma is launch #4 (the one ncu captures)
// ============================================================================
__global__ void noop_kernel() {}

// ============================================================================
// HMMA GEMM (R3-proven): g_part[sp] = A_ph @ B_ph^T over k slice
// grid (4 N-tiles, 4 M-tiles, 18 splits), 256 threads, 8 warps (4M x 2N).
// 4-stage cp.async pipeline, wait<=2.
// ============================================================================
__global__ __launch_bounds__(256, 2) void gemm_hmma() {
    extern __shared__ char smem[];
    const uint32_t sbase = smem_u32(smem);
    const int t = threadIdx.x;
    const int wid = t >> 5, lane = t & 31;

    const int n0 = blockIdx.x * BN;
    const int m0 = blockIdx.y * BM;
    const int sp = blockIdx.z;
    const int phase = sp / SUBSPLITS;            // 0: hi*hi  1: hi*lo  2: lo*hi
    const size_t ksub = (size_t)(sp % SUBSPLITS) * KSPLIT;

    const __nv_bfloat16* __restrict__ A = (phase == 2) ? gAlo : gAhi;
    const __nv_bfloat16* __restrict__ B = (phase == 1) ? gBlo : gBhi;

    // ---- loader mapping: thread loads 2 A chunks + 2 B chunks of 16B per stage
    const int lr = t >> 2;          // tile row 0..63
    const int lc = t & 3;           // 16B chunk 0..3
    const uint32_t dA1 = toff(lr, lc),        dA2 = toff(lr + 64, lc);
    const uint32_t dB1 = toff(lr, lc) + 8192, dB2 = toff(lr + 64, lc) + 8192;
    const __nv_bfloat16* pA1 = A + (size_t)(m0 + lr) * IN_DIM + ksub + lc * 8;
    const __nv_bfloat16* pA2 = pA1 + (size_t)64 * IN_DIM;
    const __nv_bfloat16* pB1 = B + (size_t)(n0 + lr) * IN_DIM + ksub + lc * 8;
    const __nv_bfloat16* pB2 = pB1 + (size_t)64 * IN_DIM;

#define LOAD_STAGE(s, kt) do {                                        \
        const uint32_t sb_ = sbase + (s) * STG_BYTES;                  \
        const size_t ko_ = (size_t)(kt) * BK;                          \
        cp16(sb_ + dA1, pA1 + ko_); cp16(sb_ + dA2, pA2 + ko_);        \
        cp16(sb_ + dB1, pB1 + ko_); cp16(sb_ + dB2, pB2 + ko_);        \
    } while (0)

    // ---- compute mapping: warp (wm, wn) owns 32x64 of C
    const int wm = wid >> 1, wn = wid & 1;
    const int fr = lane & 15, fc = lane >> 4;
    uint32_t aoff[2][2], boff[4][2];
#pragma unroll
    for (int mh = 0; mh < 2; mh++)
#pragma unroll
        for (int ks = 0; ks < 2; ks++)
            aoff[mh][ks] = toff(wm * 32 + mh * 16 + fr, ks * 2 + fc);
#pragma unroll
    for (int p = 0; p < 4; p++)
#pragma unroll
        for (int ks = 0; ks < 2; ks++)
            boff[p][ks] = 8192 + toff(wn * 64 + p * 16 + fr, ks * 2 + fc);

    float c[2][8][4];
#pragma unroll
    for (int i = 0; i < 2; i++)
#pragma unroll
        for (int j = 0; j < 8; j++)
#pragma unroll
            for (int k = 0; k < 4; k++) c[i][j][k] = 0.f;

    // ---- prologue: fill stages 0..2
#pragma unroll
    for (int s = 0; s < STAGES - 1; s++) {
        LOAD_STAGE(s, s);
        CP_COMMIT();
    }

    // ---- main loop
    for (int kt = 0; kt < NT; ++kt) {
        CP_WAIT2();
        __syncthreads();

        if (kt + STAGES - 1 < NT)
            LOAD_STAGE((kt + STAGES - 1) & (STAGES - 1), kt + STAGES - 1);
        CP_COMMIT();

        const uint32_t sb = sbase + (kt & (STAGES - 1)) * STG_BYTES;
#pragma unroll
        for (int ks = 0; ks < 2; ks++) {
            uint32_t a0[4], a1[4];
            ldsm4(a0[0], a0[1], a0[2], a0[3], sb + aoff[0][ks]);
            ldsm4(a1[0], a1[1], a1[2], a1[3], sb + aoff[1][ks]);
#pragma unroll
            for (int p = 0; p < 4; p++) {
                uint32_t r0, r1, r2, r3;
                ldsm4(r0, r1, r2, r3, sb + boff[p][ks]);
                uint32_t b0[2] = { r0, r2 };
                uint32_t b1[2] = { r1, r3 };
                mma16816(c[0][2*p],     a0, b0);
                mma16816(c[1][2*p],     a1, b0);
                mma16816(c[0][2*p + 1], a0, b1);
                mma16816(c[1][2*p + 1], a1, b1);
            }
        }
    }

    // ---- epilogue: direct fp32 stores of partials
    float* base = g_part + (size_t)sp * MPAD * NDIM;
    const int row0 = m0 + wm * 32 + (lane >> 2);
    const int col0 = n0 + wn * 64 + (lane & 3) * 2;
#pragma unroll
    for (int mi = 0; mi < 2; mi++)
#pragma unroll
        for (int j = 0; j < 8; j++) {
            const int r = row0 + mi * 16;
            const int cc = col0 + j * 8;
            *(float2*)&base[(size_t)r * NDIM + cc]       = make_float2(c[mi][j][0], c[mi][j][1]);
            *(float2*)&base[(size_t)(r + 8) * NDIM + cc] = make_float2(c[mi][j][2], c[mi][j][3]);
        }
}

// ============================================================================
// split-K reduce + bias (deterministic order, float4-vectorized)
// ============================================================================
__global__ void reduce_bias(const float* __restrict__ bias) {
    const int i4 = blockIdx.x * blockDim.x + threadIdx.x;
    const int e = i4 * 4;
    if (e >= MROWS * NDIM) return;
    const int n = e & (NDIM - 1);
    float4 s = make_float4(0.f, 0.f, 0.f, 0.f);
#pragma unroll
    for (int p = 0; p < TOTSPLITS; p++) {
        const float4 v = *(const float4*)&g_part[(size_t)p * MPAD * NDIM + e];
        s.x += v.x; s.y += v.y; s.z += v.z; s.w += v.w;
    }
    const float4 b = *(const float4*)&bias[n];
    s.x += b.x; s.y += b.y; s.z += b.z; s.w += b.w;
    *(float4*)&g_ze[e] = s;
}

// ============================================================================
// nearest codebook: argmax_k (z.c_k - 0.5||c_k||^2), tie -> min k
// ============================================================================
__global__ __launch_bounds__(512) void nearest_kernel(const float* __restrict__ cb) {
    __shared__ float zs[8][NDIM];
    __shared__ float red[512];
    __shared__ int   redi[512];
    const int t = threadIdx.x;
    const int r0 = blockIdx.x * 8;
#pragma unroll
    for (int g = 0; g < 8; g++) zs[g][t] = g_ze[(r0 + g) * NDIM + t];
    __syncthreads();
    float s[8];
#pragma unroll
    for (int g = 0; g < 8; g++) s[g] = 0.f;
    float cn = 0.f;
#pragma unroll 4
    for (int d = 0; d < NDIM; d++) {
        const float c = cb[d * NK + t];
        cn = fmaf(c, c, cn);
#pragma unroll
        for (int g = 0; g < 8; g++) s[g] = fmaf(zs[g][d], c, s[g]);
    }
    for (int g = 0; g < 8; g++) {
        red[t] = s[g] - 0.5f * cn;
        redi[t] = t;
        __syncthreads();
        for (int off = 256; off > 0; off >>= 1) {
            if (t < off) {
                const float o = red[t + off];
                const int oi = redi[t + off];
                if (o > red[t] || (o == red[t] && oi < redi[t])) { red[t] = o; redi[t] = oi; }
            }
            __syncthreads();
        }
        if (t == 0) g_idx[r0 + g] = redi[0];
        __syncthreads();
    }
}

// ============================================================================
// prototypes: mean of 5 quantized shots, L2-normalized
// ============================================================================
__global__ __launch_bounds__(512) void proto_kernel(const float* __restrict__ cb) {
    const int bw = blockIdx.x, t = threadIdx.x;
    float p = 0.f;
#pragma unroll
    for (int s = 0; s < 5; s++) p += cb[(size_t)t * NK + g_idx[bw * 5 + s]];
    p *= 0.2f;
    __shared__ float red[512];
    red[t] = p * p;
    __syncthreads();
    for (int off = 256; off > 0; off >>= 1) {
        if (t < off) red[t] += red[t + off];
        __syncthreads();
    }
    g_proto[bw * NDIM + t] = p * rsqrtf(red[0]);
}

// ============================================================================
// logits
// ============================================================================
__global__ __launch_bounds__(512) void logits_kernel(
    const float* __restrict__ cb, const float* __restrict__ tptr,
    float* __restrict__ out) {
    const int bq = blockIdx.x, t = threadIdx.x;
    const int b = bq / 75;
    const float v = cb[(size_t)t * NK + g_idx[NSHOT + bq]];
    __shared__ float red[512];
    red[t] = v * v;
    __syncthreads();
    for (int off = 256; off > 0; off >>= 1) {
        if (t < off) red[t] += red[t + off];
        __syncthreads();
    }
    const float vn = v * rsqrtf(red[0]);
    const float temp = *tptr;
    for (int w = 0; w < 5; w++) {
        __syncthreads();
        red[t] = vn * g_proto[(b * 5 + w) * NDIM + t];
        __syncthreads();
        for (int off = 256; off > 0; off >>= 1) {
            if (t < off) red[t] += red[t + off];
            __syncthreads();
        }
        if (t == 0) out[bq * 5 + w] = red[0] * temp;
    }
}

// ============================================================================
extern "C" void kernel_launch(void* const* d_in, const int* in_sizes, int n_in,
                              void* d_out, int out_size) {
    const float* xs   = (const float*)d_in[0];
    const float* xq   = (const float*)d_in[1];
    const float* W    = (const float*)d_in[2];
    const float* bias = (const float*)d_in[3];
    const float* cb   = (const float*)d_in[4];
    const float* temp = (const float*)d_in[5];
    float* out = (float*)d_out;

    cudaFuncSetAttribute(gemm_hmma, cudaFuncAttributeMaxDynamicSharedMemorySize,
                         SMEM_GEMM);

    conv_all<<<A_BLOCKS + B_BLOCKS, 256>>>(xs, xq, W);
    noop_kernel<<<1, 32>>>();   // shims: keep gemm_hmma at launch #4 for ncu
    noop_kernel<<<1, 32>>>();
    gemm_hmma<<<dim3(NDIM / BN, MPAD / BM, TOTSPLITS), 256, SMEM_GEMM>>>();
    reduce_bias<<<(MROWS * NDIM / 4 + 255) / 256, 256>>>(bias);
    nearest_kernel<<<MROWS / 8, 512>>>(cb);
    proto_kernel<<<20, 512>>>(cb);
    logits_kernel<<<300, 512>>>(cb, temp, out);
}